// round 1
// baseline (speedup 1.0000x reference)
#include <cuda_runtime.h>
#include <cstdint>

#define BB 16
#define NN 48384
#define KK 512
#define MAXD 100
#define IOU_T 0.45f
#define CONF0 0.25f

#define MASK_OFF (BB * MAXD * 7)          /* 11200 */
#define FEAT_OFF (MASK_OFF + BB * MAXD)   /* 12800 */
#define FEAT_N   (16 * 256 * 48 * 48)     /* 9437184 */

// ---------------- device scratch (static, no allocations) ----------------
__device__ float    g_scores[BB * NN];          // raw scores obj*cls
__device__ float    g_cand[BB][KK][8];          // x1,y1,x2,y2,area,obj,conf,valid
__device__ unsigned g_sup[BB][KK][16];          // suppression bitmatrix (j>i only)

// ---------------- K1: scores ----------------
__global__ void __launch_bounds__(1024) k_scores(const float* __restrict__ pred) {
    int i = blockIdx.x * 1024 + threadIdx.x;
    if (i < BB * NN) {
        // row = [cx,cy,w,h,obj,cls]; obj at +4, cls at +5; (24*i+16) is 8B aligned
        float2 oc = *reinterpret_cast<const float2*>(pred + (size_t)i * 6 + 4);
        g_scores[i] = __fmul_rn(oc.x, oc.y);
    }
}

// ---------------- K2: per-image threshold + exact top-512 select ----------------
// dynamic smem layout:
//   [0, 65536)       unsigned hist[16384]   (later aliased as u64 buf[4096])
//   [65536, 69632)   unsigned/float part[1024]
//   [69632, 69696)   misc scalars
#define SMEM_K2 69696

__global__ void __launch_bounds__(1024) k_select(const float* __restrict__ pred) {
    extern __shared__ unsigned char smem[];
    unsigned*           hist   = reinterpret_cast<unsigned*>(smem);
    unsigned long long* buf    = reinterpret_cast<unsigned long long*>(smem);
    float*              fpart  = reinterpret_cast<float*>(smem + 65536);
    unsigned*           upart  = reinterpret_cast<unsigned*>(smem + 65536);
    float*              sThr   = reinterpret_cast<float*>(smem + 69632);
    unsigned*           sBstar = reinterpret_cast<unsigned*>(smem + 69636);
    int*                sCnt   = reinterpret_cast<int*>(smem + 69640);
    int*                sTstar = reinterpret_cast<int*>(smem + 69644);

    const int img = blockIdx.x;
    const int tid = threadIdx.x;
    const float* sc = g_scores + (size_t)img * NN;

    // ---- pass 0: per-image max -> dynamic threshold ----
    float lm = 0.f;
    for (int i = tid; i < NN; i += 1024) lm = fmaxf(lm, sc[i]);
    fpart[tid] = lm;
    __syncthreads();
    for (int off = 512; off > 0; off >>= 1) {
        if (tid < off) fpart[tid] = fmaxf(fpart[tid], fpart[tid + off]);
        __syncthreads();
    }
    if (tid == 0) {
        float mv = fpart[0];
        float t = CONF0;
        for (int it = 0; it < 200 && mv < t; ++it)
            t = fmaxf(__fsub_rn(t, 0.1f), __fdiv_rn(t, 10.0f));
        *sThr = t;
    }
    __syncthreads();
    const float thr = *sThr;

    // ---- pass 1: histogram of masked score bits >> 16 (skip zeros!) ----
    for (int i = tid; i < 16384; i += 1024) hist[i] = 0u;
    __syncthreads();
    for (int i = tid; i < NN; i += 1024) {
        float s = sc[i];
        float m = (s >= thr) ? s : 0.f;
        unsigned b = __float_as_uint(m) >> 16;
        if (b != 0u) atomicAdd(&hist[b], 1u);   // zeros counted analytically
    }
    __syncthreads();

    // ---- suffix scan to find boundary bucket B*: max b with cum(b) >= 512 ----
    unsigned p = 0;
    #pragma unroll
    for (int b = 0; b < 16; ++b) p += hist[tid * 16 + b];
    upart[tid] = p;
    __syncthreads();
    for (int off = 1; off < 1024; off <<= 1) {
        unsigned v = (tid + off < 1024) ? upart[tid + off] : 0u;
        __syncthreads();
        upart[tid] += v;
        __syncthreads();
    }
    // cum(16*t) = upart[t] counts only positives; cum(0) == NN (zeros included)
    if (tid == 0 && upart[0] < KK) *sTstar = 0;      // degenerate: boundary in bucket 0
    if (upart[tid] >= KK && (tid == 1023 || upart[tid + 1] < KK)) *sTstar = tid;
    __syncthreads();
    if (tid == 0) {
        int t = *sTstar;
        unsigned bst;
        if (upart[0] < KK) {
            bst = 0u;                                  // take everything (handled via clamp)
        } else {
            unsigned c = (t < 1023) ? upart[t + 1] : 0u;
            bst = (unsigned)(t * 16);
            for (int b = t * 16 + 15; b >= t * 16; --b) {
                if (b == 0) { bst = 0u; break; }
                c += hist[b];
                if (c >= KK) { bst = (unsigned)b; break; }
            }
        }
        *sBstar = bst;
        *sCnt = 0;
    }
    __syncthreads();
    const unsigned bstar = *sBstar;

    // ---- pass 2: gather candidates (aliases hist region — hist dead now) ----
    for (int i = tid; i < NN; i += 1024) {
        float s = sc[i];
        float m = (s >= thr) ? s : 0.f;
        unsigned bits = __float_as_uint(m);
        if ((bits >> 16) >= bstar) {
            int pz = atomicAdd(sCnt, 1);
            if (pz < 4096)
                buf[pz] = ((unsigned long long)bits << 32) |
                          (unsigned long long)(0xFFFFFFFFu - (unsigned)i);
        }
    }
    __syncthreads();
    int cnt = *sCnt; if (cnt > 4096) cnt = 4096;
    for (int i = cnt + tid; i < 4096; i += 1024) buf[i] = 0ull;
    __syncthreads();

    // ---- bitonic sort, descending (key = scorebits<<32 | ~idx => exact top_k order) ----
    for (int k = 2; k <= 4096; k <<= 1) {
        for (int j = k >> 1; j > 0; j >>= 1) {
            __syncthreads();
            #pragma unroll
            for (int r = 0; r < 4; ++r) {
                int i = tid + r * 1024;
                int l = i ^ j;
                if (l > i) {
                    unsigned long long a = buf[i], b = buf[l];
                    bool up = ((i & k) == 0);
                    if ((a < b) == up) { buf[i] = b; buf[l] = a; }
                }
            }
        }
    }
    __syncthreads();

    // ---- materialize 512 candidates ----
    if (tid < KK) {
        unsigned long long key = buf[tid];
        unsigned bits = (unsigned)(key >> 32);
        unsigned idx  = 0xFFFFFFFFu - (unsigned)(key & 0xFFFFFFFFull);
        float x1 = 0.f, y1 = 0.f, x2 = 0.f, y2 = 0.f, ar = 0.f, ob = 0.f, cf = 0.f, vd = 0.f;
        if (bits != 0u && idx < (unsigned)NN) {
            const float* row = pred + ((size_t)img * NN + idx) * 6;
            float cx = row[0], cy = row[1], w = row[2], h = row[3];
            ob = row[4]; cf = row[5];
            float hw = __fmul_rn(w, 0.5f), hh = __fmul_rn(h, 0.5f);
            x1 = __fsub_rn(cx, hw); y1 = __fsub_rn(cy, hh);
            x2 = __fadd_rn(cx, hw); y2 = __fadd_rn(cy, hh);
            ar = __fmul_rn(fmaxf(__fsub_rn(x2, x1), 0.f),
                           fmaxf(__fsub_rn(y2, y1), 0.f));
            vd = 1.f;
        }
        float* cd = g_cand[img][tid];
        cd[0] = x1; cd[1] = y1; cd[2] = x2; cd[3] = y2;
        cd[4] = ar; cd[5] = ob; cd[6] = cf; cd[7] = vd;
    }
}

// ---------------- K3: suppression bitmatrix (parallel across 8x16 blocks) ----------------
__global__ void __launch_bounds__(256) k_supmat() {
    __shared__ float bx1[KK], by1[KK], bx2[KK], by2[KK], bar[KK];
    const int img = blockIdx.y;
    const int chunk = blockIdx.x;  // 64 rows per chunk
    const int tid = threadIdx.x;
    for (int c = tid; c < KK; c += 256) {
        const float* cd = g_cand[img][c];
        bx1[c] = cd[0]; by1[c] = cd[1]; bx2[c] = cd[2]; by2[c] = cd[3]; bar[c] = cd[4];
    }
    __syncthreads();
    #pragma unroll
    for (int s = 0; s < 4; ++s) {
        int t = tid + s * 256;              // 0..1023 => (row-in-chunk, word)
        int i = chunk * 64 + (t >> 4);
        int w = t & 15;
        float x1 = bx1[i], yy1 = by1[i], x2 = bx2[i], yy2 = by2[i], ai = bar[i];
        unsigned bits = 0u;
        int jbase = w * 32;
        #pragma unroll 8
        for (int l = 0; l < 32; ++l) {
            int j = jbase + l;
            if (j > i) {
                float ltx = fmaxf(x1,  bx1[j]);
                float lty = fmaxf(yy1, by1[j]);
                float rbx = fminf(x2,  bx2[j]);
                float rby = fminf(yy2, by2[j]);
                float wd = fmaxf(__fsub_rn(rbx, ltx), 0.f);
                float hg = fmaxf(__fsub_rn(rby, lty), 0.f);
                float inter = __fmul_rn(wd, hg);
                float den = __fadd_rn(__fsub_rn(__fadd_rn(ai, bar[j]), inter), 1e-9f);
                float iou = __fdiv_rn(inter, den);     // exact rn div, matches XLA
                if (iou > IOU_T) bits |= (1u << l);
            }
        }
        g_sup[img][i][w] = bits;
    }
}

// ---------------- K4: sequential keep-reduction + outputs ----------------
__global__ void __launch_bounds__(128) k_nms_out(float* __restrict__ out) {
    __shared__ __align__(16) unsigned s_sup[KK * 16];
    __shared__ unsigned s_kw[16];
    __shared__ int s_pfx[16];
    __shared__ int s_slot[MAXD];
    const int img = blockIdx.x;
    const int tid = threadIdx.x;

    const uint4* src = reinterpret_cast<const uint4*>(&g_sup[img][0][0]);
    uint4* dst = reinterpret_cast<uint4*>(s_sup);
    for (int i = tid; i < (KK * 16) / 4; i += 128) dst[i] = src[i];
    if (tid < 16) s_kw[tid] = 0u;
    __syncthreads();
    for (int i = tid; i < KK; i += 128)
        if (g_cand[img][i][7] != 0.f) atomicOr(&s_kw[i >> 5], 1u << (i & 31));
    __syncthreads();

    if (tid < 32) {
        const int lane = tid;
        unsigned Kw = (lane < 16) ? s_kw[lane] : 0u;
        for (int t = 0; t < 16; ++t) {
            unsigned m = __shfl_sync(0xffffffffu, Kw, t);
            // intra-tile sequential resolve (all lanes redundantly)
            #pragma unroll
            for (int l = 0; l < 32; ++l)
                if ((m >> l) & 1u) m &= ~s_sup[(t * 32 + l) * 16 + t];
            if (lane == t) Kw = m;
            // cross-tile: kept members of tile t suppress later words
            if (lane > t && lane < 16) {
                unsigned c = 0u;
                #pragma unroll
                for (int l = 0; l < 32; ++l)
                    if ((m >> l) & 1u) c |= s_sup[(t * 32 + l) * 16 + lane];
                Kw &= ~c;
            }
        }
        if (lane < 16) s_kw[lane] = Kw;
    }
    __syncthreads();

    if (tid == 0) {
        int acc = 0;
        for (int w = 0; w < 16; ++w) { s_pfx[w] = acc; acc += __popc(s_kw[w]); }
    }
    if (tid < MAXD) s_slot[tid] = -1;
    __syncthreads();
    for (int i = tid; i < KK; i += 128) {
        int w = i >> 5, b = i & 31;
        if ((s_kw[w] >> b) & 1u) {
            int r = s_pfx[w] + __popc(s_kw[w] & ((1u << b) - 1u));
            if (r < MAXD) s_slot[r] = i;
        }
    }
    __syncthreads();
    for (int s = tid; s < MAXD; s += 128) {
        int c = s_slot[s];
        float r0 = 0.f, r1 = 0.f, r2 = 0.f, r3 = 0.f, r4 = 0.f, r5 = 0.f, mk = 0.f;
        if (c >= 0) {
            const float* cd = g_cand[img][c];
            r0 = cd[0]; r1 = cd[1]; r2 = cd[2]; r3 = cd[3];
            r4 = cd[5]; r5 = cd[6]; mk = 1.f;
        }
        float* o = out + (size_t)img * (MAXD * 7) + (size_t)s * 7;
        o[0] = r0; o[1] = r1; o[2] = r2; o[3] = r3; o[4] = r4; o[5] = r5; o[6] = 0.f;
        out[MASK_OFF + img * MAXD + s] = mk;
    }
}

// ---------------- launcher ----------------
extern "C" void kernel_launch(void* const* d_in, const int* in_sizes, int n_in,
                              void* d_out, int out_size) {
    const float* pred = (const float*)d_in[0];
    const float* feat = (const float*)d_in[1];
    float* out = (float*)d_out;

    cudaFuncSetAttribute(k_select, cudaFuncAttributeMaxDynamicSharedMemorySize, SMEM_K2);

    // features pass-through (bulk of DRAM traffic)
    cudaMemcpyAsync(out + FEAT_OFF, feat, (size_t)FEAT_N * sizeof(float),
                    cudaMemcpyDeviceToDevice, 0);

    k_scores<<<(BB * NN) / 1024, 1024>>>(pred);
    k_select<<<BB, 1024, SMEM_K2>>>(pred);
    k_supmat<<<dim3(8, BB), 256>>>();
    k_nms_out<<<BB, 128>>>(out);
}